// round 17
// baseline (speedup 1.0000x reference)
#include <cuda_runtime.h>
#include <cstdint>

#define NB    4
#define NCATT 8
#define ND    48
#define NH    128
#define NW    256
#define NCF   80
#define NEMB  64
#define NHW   (NH*NW)          // 32768

// Scratch (device globals: allocation-free contract)
__device__ float g_Q[NB*NEMB*NHW];      // 33.5 MB
__device__ float g_K[NB*NEMB*NHW];
__device__ float g_V[NB*NEMB*NHW];
__device__ float g_delta[NB*NCATT*NHW]; // 16.8 MB
// fp16 weight fragments, m16n8k16 B-operand layout:
// u32 idx = ((s*24 + t)*32 + lane)*2 + j ; s<5, t<24
__device__ uint32_t g_WfragH[5*24*32*2];

__device__ __forceinline__ uint32_t smem_u32(const void* p) {
    uint32_t a;
    asm("{ .reg .u64 t; cvta.to.shared.u64 t, %1; cvt.u32.u64 %0, t; }"
        : "=r"(a) : "l"(p));
    return a;
}
// pack {lo, hi} floats -> f16x2 (first asm source lands in HIGH half)
__device__ __forceinline__ uint32_t pkh2(float lo, float hi) {
    uint32_t r;
    asm("cvt.rn.f16x2.f32 %0, %1, %2;" : "=r"(r) : "f"(hi), "f"(lo));
    return r;
}

// ---------------------------------------------------------------------------
// K0: fp16 B-operand fragment image for m16n8k16 (FROZEN).
// ---------------------------------------------------------------------------
__global__ void wfrag_kernel(const float* __restrict__ Wq,
                             const float* __restrict__ Wk,
                             const float* __restrict__ Wv) {
    for (int idx = threadIdx.x; idx < 5*24*32*2; idx += blockDim.x) {
        int j  = idx & 1;
        int pi = idx >> 1;
        int l  = pi & 31;
        int tt = pi >> 5;
        int t  = tt % 24, s = tt / 24;
        int e  = t*8 + (l >> 2);
        int k  = s*16 + (l & 3)*2 + j*8;     // 0..78, k+1 <= 79
        const float* W = (e < 64) ? (Wq + e*NCF)
                       : (e < 128) ? (Wk + (e-64)*NCF)
                                   : (Wv + (e-128)*NCF);
        g_WfragH[idx] = pkh2(W[k], W[k+1]);
    }
}

// ---------------------------------------------------------------------------
// K1: QKV projection via mma.sync m16n8k16 fp16 (FROZEN from round 15).
// ---------------------------------------------------------------------------
#define APAD    132
#define A_FLOAT (80*APAD)          // floats per A buffer
#define A_BYTES (A_FLOAT*4)        // 42240
#define B_BYTES (5*24*32*2*4)      // 30720
#define SMEM1   (2*A_BYTES + B_BYTES)   // 115200
#define NTILES  (NB*256)           // 1024

__device__ __forceinline__ void mma_f16(float* c, const uint32_t* a,
                                        const uint32_t* b) {
    asm("mma.sync.aligned.m16n8k16.row.col.f32.f16.f16.f32 "
        "{%0,%1,%2,%3}, {%4,%5,%6,%7}, {%8,%9}, {%0,%1,%2,%3};"
        : "+f"(c[0]), "+f"(c[1]), "+f"(c[2]), "+f"(c[3])
        : "r"(a[0]), "r"(a[1]), "r"(a[2]), "r"(a[3]), "r"(b[0]), "r"(b[1]));
}
#define CPA16(dst, src) \
    asm volatile("cp.async.ca.shared.global [%0], [%1], 16;" \
                 :: "r"(dst), "l"(src))
#define CP_COMMIT() asm volatile("cp.async.commit_group;" ::: "memory")
#define CP_WAIT3()  asm volatile("cp.async.wait_group 3;" ::: "memory")
#define CP_WAIT2()  asm volatile("cp.async.wait_group 2;" ::: "memory")
#define CP_WAIT1()  asm volatile("cp.async.wait_group 1;" ::: "memory")
#define CP_WAIT0()  asm volatile("cp.async.wait_group 0;" ::: "memory")

__device__ __forceinline__ void a_load(uint32_t dstA, const float* __restrict__ feat,
                                       int tile, int tid) {
    const int b  = tile >> 8;
    const int n0 = (tile & 255) << 7;
    const float* srcA = feat + (size_t)b*NCF*NHW + n0;
#pragma unroll
    for (int i = 0; i < 5; i++) {                 // 2560 chunks / 512 thr
        const int idx = tid + i*512;
        const int k = idx >> 5, c = idx & 31;
        CPA16(dstA + (uint32_t)(k*APAD + c*4)*4, srcA + (size_t)k*NHW + c*4);
    }
}

__global__ __launch_bounds__(512, 1)
void qkv_mma_kernel(const float* __restrict__ feat) {
    extern __shared__ float sm[];
    float* shA[2] = { sm, sm + A_FLOAT };
    float* shB    = sm + 2*A_FLOAT;
    const int tid  = threadIdx.x;
    const int lane = tid & 31;
    const int wid  = tid >> 5;
    const uint32_t sbase = smem_u32(sm);
    const uint32_t aAddr[2] = { sbase, sbase + A_BYTES };

    {
        const uint32_t bb = sbase + 2*A_BYTES;
        const float4* srcB = reinterpret_cast<const float4*>(g_WfragH);
        for (int idx = tid; idx < B_BYTES/16; idx += 512)
            CPA16(bb + idx*16, srcB + idx);
        if ((int)blockIdx.x < NTILES)
            a_load(aAddr[0], feat, blockIdx.x, tid);
        CP_COMMIT();
    }

    const int pxg = wid & 7;            // 8 groups of 16 px
    const int eh  = wid >> 3;           // 2 e-halves of 96
    const int px0 = pxg*16;
    const int l4  = lane >> 2, lm4 = lane & 3;
    const float* bBase = shB + eh*12*64 + lane*2;

    int i = 0;
    for (int tile = blockIdx.x; tile < NTILES; tile += gridDim.x, i++) {
        const int cur = i & 1;
        const int nxt = cur ^ 1;
        __syncthreads();
        const int ntile = tile + gridDim.x;
        if (ntile < NTILES) a_load(aAddr[nxt], feat, ntile, tid);
        CP_COMMIT();
        CP_WAIT1();
        __syncthreads();

        const float* curA = shA[cur];
        float acc[12][4];
#pragma unroll
        for (int t = 0; t < 12; t++)
#pragma unroll
            for (int j = 0; j < 4; j++) acc[t][j] = 0.0f;

        const float* aCol = curA + px0 + l4;
#pragma unroll
        for (int s = 0; s < 5; s++) {
            const float* ap = aCol + (s*16 + lm4*2)*APAD;
            float fa = ap[0],        fb = ap[APAD];
            float fc = ap[8],        fd = ap[APAD + 8];
            float fe = ap[8*APAD],   ff = ap[9*APAD];
            float fg = ap[8*APAD+8], fh = ap[9*APAD+8];
            uint32_t A[4];
            A[0] = pkh2(fa, fb);
            A[1] = pkh2(fc, fd);
            A[2] = pkh2(fe, ff);
            A[3] = pkh2(fg, fh);
            uint32_t B[12][2];
#pragma unroll
            for (int t = 0; t < 12; t++) {
                float2 bv = *reinterpret_cast<const float2*>(bBase + (s*24 + t)*64);
                B[t][0] = __float_as_uint(bv.x);
                B[t][1] = __float_as_uint(bv.y);
            }
#pragma unroll
            for (int t = 0; t < 12; t++)
                mma_f16(acc[t], A, B[t]);
        }

        const int b  = tile >> 8;
        const int n0 = (tile & 255) << 7;
#pragma unroll
        for (int t = 0; t < 12; t++) {
            const int e0 = (eh*12 + t)*8 + lm4*2;
            float* seg = (e0 < 64) ? g_Q : ((e0 < 128) ? g_K : g_V);
            const int ch0 = e0 & 63;
            float* d0 = seg + (size_t)(b*NEMB + ch0)*NHW + n0 + px0 + l4;
            float* d1 = d0 + NHW;
            d0[0] = acc[t][0];
            d1[0] = acc[t][1];
            d0[8] = acc[t][2];
            d1[8] = acc[t][3];
        }
    }
}

// ---------------------------------------------------------------------------
// K2: local windowed MHA — QUAD-buffered.  All 4 K segments issued up front
// (4-deep MLP), consumed with wait_group 3/2/1/0; one barrier at the K->V
// buffer-reuse transition; V identical.  smem = 4*27648 + 2048 = 112640 B,
// 2 blocks/SM (225 KB <= 228 KB).
// ---------------------------------------------------------------------------
#define SEG_CH   16
#define TROWS    6
#define ROW_F    72                        // floats per smem row
#define CH_STR   (TROWS*ROW_F)             // 432 floats per channel
#define SEG_F    (SEG_CH*CH_STR)           // 6912 floats = 27648 B
#define NCHUNK   (SEG_CH*TROWS*18)         // 1728 16B chunks per segment

__device__ __forceinline__ void seg_load(float* buf, const float* __restrict__ src,
                                         int b, int e0, int y0, int x0, int tid) {
    const float* sb = src + (size_t)(b*NEMB + e0)*NHW;
#pragma unroll
    for (int i = 0; i < 7; i++) {
        const int idx = tid + i*256;
        if (i < 6 || idx < NCHUNK) {
            const int c18 = idx % 18;
            const int t6  = idx / 18;
            const int rr  = t6 % 6;
            const int ch  = t6 / 6;
            const int gy  = y0 - 1 + rr;
            const int gxs = x0 - 4 + c18*4;
            float* d = buf + ch*CH_STR + rr*ROW_F + c18*4;
            const bool ok = ((unsigned)gy < NH) & ((unsigned)gxs < (NW-3));
            if (ok) {
                const float* s = sb + (size_t)ch*NHW + (size_t)gy*NW + gxs;
                asm volatile("cp.async.ca.shared.global [%0], [%1], 16;"
                             :: "r"(smem_u32(d)), "l"(s));
            } else {
                *reinterpret_cast<float4*>(d) = make_float4(0.f,0.f,0.f,0.f);
            }
        }
    }
}

template<int E0>
__device__ __forceinline__ void score_seg(const float* sh, float (&sc)[36],
                                          const float (&Qr)[64], int bx) {
#pragma unroll
    for (int d = 0; d < 16; d++)
#pragma unroll
        for (int p = 0; p < 9; p++)
#pragma unroll
            for (int h = 0; h < 4; h++) {
                const int q = h*16 + d;
                const int L = p*64 + q;
                const int e = L/9, wi = L % 9;
                if (e >= E0 && e < E0 + SEG_CH) {
                    const int dyy = wi/3, dxx = wi % 3;
                    sc[h*9+p] += Qr[q] * sh[(e-E0)*CH_STR + dyy*ROW_F + dxx + bx];
                }
            }
}

template<int E0>
__device__ __forceinline__ void ctx_seg(const float* sh, float (&ctx)[64],
                                        const float (&sc)[36], int bx) {
#pragma unroll
    for (int p = 0; p < 9; p++)
#pragma unroll
        for (int d = 0; d < 16; d++)
#pragma unroll
            for (int h = 0; h < 4; h++) {
                const int q = h*16 + d;
                const int L = p*64 + q;
                const int e = L/9, wi = L % 9;
                if (e >= E0 && e < E0 + SEG_CH) {
                    const int dyy = wi/3, dxx = wi % 3;
                    ctx[q] += sc[h*9+p] * sh[(e-E0)*CH_STR + dyy*ROW_F + dxx + bx];
                }
            }
}

__global__ __launch_bounds__(256, 2)
void attn_kernel(const float* __restrict__ dispgap, const float* __restrict__ Wo) {
    extern __shared__ float smem2[];
    float* B0    = smem2;
    float* B1    = smem2 + SEG_F;
    float* B2    = smem2 + 2*SEG_F;
    float* B3    = smem2 + 3*SEG_F;
    float* wo_sh = smem2 + 4*SEG_F;
    const int b   = blockIdx.z;
    const int y0  = blockIdx.y * 4;
    const int x0  = blockIdx.x * 64;
    const int tid = threadIdx.x;
    const int x   = tid & 63;
    const int yy  = tid >> 6;                  // 0..3
    const int bx  = yy*ROW_F + x + 3;          // dxx=0 -> gx = x0 + x - 1

    for (int i = tid; i < NCATT*NEMB; i += 256) wo_sh[i] = Wo[i];

    // issue ALL K segments (4-deep)
    seg_load(B0, g_K, b, 0,  y0, x0, tid);  CP_COMMIT();
    seg_load(B1, g_K, b, 16, y0, x0, tid);  CP_COMMIT();
    seg_load(B2, g_K, b, 32, y0, x0, tid);  CP_COMMIT();
    seg_load(B3, g_K, b, 48, y0, x0, tid);  CP_COMMIT();

    float Qr[64];
#pragma unroll
    for (int e = 0; e < 64; e++)
        Qr[e] = g_Q[(size_t)(b*NEMB + e)*NHW + (y0+yy)*NW + x0 + x];

    float sc[36];
#pragma unroll
    for (int i = 0; i < 36; i++) sc[i] = 0.0f;

    CP_WAIT3(); __syncthreads();
    score_seg<0>(B0, sc, Qr, bx);
    CP_WAIT2(); __syncthreads();
    score_seg<16>(B1, sc, Qr, bx);
    CP_WAIT1(); __syncthreads();
    score_seg<32>(B2, sc, Qr, bx);
    CP_WAIT0(); __syncthreads();
    score_seg<48>(B3, sc, Qr, bx);

    // softmax over p (SCALE = 0.25 folded in)
#pragma unroll
    for (int h = 0; h < 4; h++) {
        float m = sc[h*9];
#pragma unroll
        for (int p = 1; p < 9; p++) m = fmaxf(m, sc[h*9+p]);
        float s = 0.0f;
#pragma unroll
        for (int p = 0; p < 9; p++) {
            float ev = __expf(0.25f*(sc[h*9+p] - m));
            sc[h*9+p] = ev;
            s += ev;
        }
        float inv = __fdividef(1.0f, s);
#pragma unroll
        for (int p = 0; p < 9; p++) sc[h*9+p] *= inv;
    }

    __syncthreads();                   // all K-buffer reads complete
    // issue ALL V segments (reusing the 4 buffers)
    seg_load(B0, g_V, b, 0,  y0, x0, tid);  CP_COMMIT();
    seg_load(B1, g_V, b, 16, y0, x0, tid);  CP_COMMIT();
    seg_load(B2, g_V, b, 32, y0, x0, tid);  CP_COMMIT();
    seg_load(B3, g_V, b, 48, y0, x0, tid);  CP_COMMIT();

    float ctx[64];
#pragma unroll
    for (int i = 0; i < 64; i++) ctx[i] = 0.0f;

    CP_WAIT3(); __syncthreads();
    ctx_seg<0>(B0, ctx, sc, bx);
    CP_WAIT2(); __syncthreads();
    ctx_seg<16>(B1, ctx, sc, bx);
    CP_WAIT1(); __syncthreads();
    ctx_seg<32>(B2, ctx, sc, bx);
    CP_WAIT0(); __syncthreads();
    ctx_seg<48>(B3, ctx, sc, bx);

    // out-projection (wo_sh reads are warp-uniform -> broadcast)
    float outv[8];
#pragma unroll
    for (int a = 0; a < 8; a++) outv[a] = 0.0f;
#pragma unroll
    for (int q = 0; q < 64; q++)
#pragma unroll
        for (int a = 0; a < 8; a++)
            outv[a] += ctx[q] * wo_sh[a*64 + q];

    const int gy = y0 + yy;
    const float dg = dispgap[b*NHW + gy*NW + x0 + x];
    const bool zero = (dg >= 2.0f);
#pragma unroll
    for (int a = 0; a < 8; a++)
        g_delta[((b*NCATT + a)*NH + gy)*NW + x0 + x] = zero ? 0.0f : outv[a];
}

// ---------------------------------------------------------------------------
// K3: broadcast add (FROZEN — 75% DRAM, at practical roofline).
// ---------------------------------------------------------------------------
#define TOT4     (NB*NCATT*ND*NHW/4)       // 12582912
#define K3J      4
#define K3STRIDE (TOT4/K3J)                // 3145728

__global__ void add_kernel(const float* __restrict__ attn, float* __restrict__ out) {
    const int gid = blockIdx.x * blockDim.x + threadIdx.x;
#pragma unroll
    for (int j = 0; j < K3J; j++) {
        const int i4 = gid + j*K3STRIDE;
        float4 a = __ldcs(reinterpret_cast<const float4*>(attn) + i4);
        const int inner = i4 & (NHW/4 - 1);
        const int ba    = (i4 >> 13) / ND;
        float4 dl = __ldg(reinterpret_cast<const float4*>(g_delta) + ba*(NHW/4) + inner);
        a.x += dl.x; a.y += dl.y; a.z += dl.z; a.w += dl.w;
        __stcs(reinterpret_cast<float4*>(out) + i4, a);
    }
}

// ---------------------------------------------------------------------------
extern "C" void kernel_launch(void* const* d_in, const int* in_sizes, int n_in,
                              void* d_out, int out_size) {
    const float* attn_vol = (const float*)d_in[0];
    const float* feat     = (const float*)d_in[1];
    const float* dispgap  = (const float*)d_in[2];
    const float* Wq       = (const float*)d_in[3];
    const float* Wk       = (const float*)d_in[4];
    const float* Wv       = (const float*)d_in[5];
    const float* Wo       = (const float*)d_in[6];
    float* out = (float*)d_out;

    const int smem2 = (4*SEG_F + NCATT*NEMB) * 4;   // 110592 + 2048 = 112640 B
    cudaFuncSetAttribute(qkv_mma_kernel,
                         cudaFuncAttributeMaxDynamicSharedMemorySize, SMEM1);
    cudaFuncSetAttribute(attn_kernel,
                         cudaFuncAttributeMaxDynamicSharedMemorySize, smem2);

    wfrag_kernel<<<1, 512>>>(Wq, Wk, Wv);
    qkv_mma_kernel<<<148, 512, SMEM1>>>(feat);
    attn_kernel<<<dim3(NW/64, NH/4, NB), 256, smem2>>>(dispgap, Wo);
    add_kernel<<<K3STRIDE/256, 256>>>(attn_vol, out);
}